// round 5
// baseline (speedup 1.0000x reference)
#include <cuda_runtime.h>
#include <cstdint>

// ---------------------------------------------------------------------------
// HopfActivCpx: dz/dt = (a - b*|z|^2) * z, 50 DOPRI5 steps (must match the
// reference's discrete trajectory — closed form fails the 1e-3 gate).
// 6 elements per thread = 3 independent f32x2 (packed-fp32) groups:
// 24 concurrent FFMA2 chains per SMSP to cover lat=4/rt=2 bubbles.
// ---------------------------------------------------------------------------

typedef unsigned long long u64;

__device__ __forceinline__ u64 pk(float lo, float hi) {
    u64 r;
    asm("mov.b64 %0, {%1, %2};" : "=l"(r) : "f"(lo), "f"(hi));
    return r;
}
__device__ __forceinline__ u64 pk2(float2 v) { return pk(v.x, v.y); }
__device__ __forceinline__ float2 up(u64 a) {
    float2 v;
    asm("mov.b64 {%0, %1}, %2;" : "=f"(v.x), "=f"(v.y) : "l"(a));
    return v;
}
__device__ __forceinline__ u64 f2fma(u64 a, u64 b, u64 c) {
    u64 d;
    asm("fma.rn.f32x2 %0, %1, %2, %3;" : "=l"(d) : "l"(a), "l"(b), "l"(c));
    return d;
}
__device__ __forceinline__ u64 f2mul(u64 a, u64 b) {
    u64 d;
    asm("mul.rn.f32x2 %0, %1, %2;" : "=l"(d) : "l"(a), "l"(b));
    return d;
}

// Hopf RHS: f(z) = (a - b*|z|^2) * z.  NBr/NBi hold -b.  NEG1 = (-1,-1).
// 9 fma-pipe ops, depth 5, single pipe.
__device__ __forceinline__ void feval(u64 zr, u64 zi,
                                      u64 Ar, u64 Ai, u64 NBr, u64 NBi, u64 NEG1,
                                      u64& fr, u64& fi) {
    u64 s  = f2fma(zi, zi, f2mul(zr, zr));   // |z|^2
    u64 cr = f2fma(NBr, s, Ar);              // a_re - b_re*s
    u64 ci = f2fma(NBi, s, Ai);              // a_im - b_im*s
    u64 p  = f2mul(cr, zr);
    u64 q  = f2mul(ci, zi);
    fr = f2fma(q, NEG1, p);                  // cr*zr - ci*zi
    fi = f2fma(ci, zr, f2mul(cr, zi));       // cr*zi + ci*zr
}

__device__ __forceinline__ u64 hcoef(float h, double a) {
    float c = (float)a;      // coefficient rounded to f32 (JAX weak typing)
    float v = h * c;         // fold h in once
    return pk(v, v);
}

#define NG 3

__global__ void __launch_bounds__(256, 2)
hopf_dopri5_kernel(const float2* __restrict__ re_z, const float2* __restrict__ im_z,
                   const float2* __restrict__ re_a, const float2* __restrict__ im_a,
                   const float2* __restrict__ re_b, const float2* __restrict__ im_b,
                   const int*    __restrict__ unts,
                   float2* __restrict__ out, int npairs, int gstride) {
    int t = blockIdx.x * blockDim.x + threadIdx.x;
    if (t >= gstride) return;

    // h = float32((2pi - 2pi/unts) / 50), fp64 like the reference
    const double TWO_PI = 6.283185307179586476925286766559;
    double uu = (double)unts[0];
    float h = (float)((TWO_PI - TWO_PI / uu) / 50.0);

    const u64 HA21 = hcoef(h, 1.0 / 5.0);
    const u64 HA31 = hcoef(h, 3.0 / 40.0);
    const u64 HA32 = hcoef(h, 9.0 / 40.0);
    const u64 HA41 = hcoef(h, 44.0 / 45.0);
    const u64 HA42 = hcoef(h, -56.0 / 15.0);
    const u64 HA43 = hcoef(h, 32.0 / 9.0);
    const u64 HA51 = hcoef(h, 19372.0 / 6561.0);
    const u64 HA52 = hcoef(h, -25360.0 / 2187.0);
    const u64 HA53 = hcoef(h, 64448.0 / 6561.0);
    const u64 HA54 = hcoef(h, -212.0 / 729.0);
    const u64 HA61 = hcoef(h, 9017.0 / 3168.0);
    const u64 HA62 = hcoef(h, -355.0 / 33.0);
    const u64 HA63 = hcoef(h, 46732.0 / 5247.0);
    const u64 HA64 = hcoef(h, 49.0 / 176.0);
    const u64 HA65 = hcoef(h, -5103.0 / 18656.0);
    const u64 HB1  = hcoef(h, 35.0 / 384.0);
    const u64 HB3  = hcoef(h, 500.0 / 1113.0);
    const u64 HB4  = hcoef(h, 125.0 / 192.0);
    const u64 HB5  = hcoef(h, -2187.0 / 6784.0);
    const u64 HB6  = hcoef(h, 11.0 / 84.0);
    const u64 NEG1 = pk(-1.0f, -1.0f);

    // Grid-strided pair indices (coalesced); clamp the single overhang pair.
    int idx[NG];
    bool ok[NG];
    #pragma unroll
    for (int g = 0; g < NG; ++g) {
        int p = t + g * gstride;
        ok[g]  = (p < npairs);
        idx[g] = ok[g] ? p : (npairs - 1);
    }

    u64 Zr[NG], Zi[NG], Ar[NG], Ai[NG], NBr[NG], NBi[NG];
    #pragma unroll
    for (int g = 0; g < NG; ++g) {
        Zr[g] = pk2(re_z[idx[g]]);
        Zi[g] = pk2(im_z[idx[g]]);
        Ar[g] = pk2(re_a[idx[g]]);
        Ai[g] = pk2(im_a[idx[g]]);
        float2 brv = re_b[idx[g]], biv = im_b[idx[g]];
        NBr[g] = pk(-brv.x, -brv.y);
        NBi[g] = pk(-biv.x, -biv.y);
    }

    #pragma unroll 1
    for (int it = 0; it < 50; ++it) {
        u64 k1r[NG], k1i[NG], k2r[NG], k2i[NG], k3r[NG], k3i[NG];
        u64 k4r[NG], k4i[NG], k5r[NG], k5i[NG], k6r[NG], k6i[NG];
        u64 zr[NG], zi[NG];

        #pragma unroll
        for (int g = 0; g < NG; ++g)
            feval(Zr[g], Zi[g], Ar[g], Ai[g], NBr[g], NBi[g], NEG1, k1r[g], k1i[g]);

        #pragma unroll
        for (int g = 0; g < NG; ++g) {
            zr[g] = f2fma(HA21, k1r[g], Zr[g]);
            zi[g] = f2fma(HA21, k1i[g], Zi[g]);
        }
        #pragma unroll
        for (int g = 0; g < NG; ++g)
            feval(zr[g], zi[g], Ar[g], Ai[g], NBr[g], NBi[g], NEG1, k2r[g], k2i[g]);

        #pragma unroll
        for (int g = 0; g < NG; ++g) {
            zr[g] = f2fma(HA31, k1r[g], Zr[g]); zr[g] = f2fma(HA32, k2r[g], zr[g]);
            zi[g] = f2fma(HA31, k1i[g], Zi[g]); zi[g] = f2fma(HA32, k2i[g], zi[g]);
        }
        #pragma unroll
        for (int g = 0; g < NG; ++g)
            feval(zr[g], zi[g], Ar[g], Ai[g], NBr[g], NBi[g], NEG1, k3r[g], k3i[g]);

        #pragma unroll
        for (int g = 0; g < NG; ++g) {
            zr[g] = f2fma(HA41, k1r[g], Zr[g]); zr[g] = f2fma(HA42, k2r[g], zr[g]);
            zr[g] = f2fma(HA43, k3r[g], zr[g]);
            zi[g] = f2fma(HA41, k1i[g], Zi[g]); zi[g] = f2fma(HA42, k2i[g], zi[g]);
            zi[g] = f2fma(HA43, k3i[g], zi[g]);
        }
        #pragma unroll
        for (int g = 0; g < NG; ++g)
            feval(zr[g], zi[g], Ar[g], Ai[g], NBr[g], NBi[g], NEG1, k4r[g], k4i[g]);

        #pragma unroll
        for (int g = 0; g < NG; ++g) {
            zr[g] = f2fma(HA51, k1r[g], Zr[g]); zr[g] = f2fma(HA52, k2r[g], zr[g]);
            zr[g] = f2fma(HA53, k3r[g], zr[g]); zr[g] = f2fma(HA54, k4r[g], zr[g]);
            zi[g] = f2fma(HA51, k1i[g], Zi[g]); zi[g] = f2fma(HA52, k2i[g], zi[g]);
            zi[g] = f2fma(HA53, k3i[g], zi[g]); zi[g] = f2fma(HA54, k4i[g], zi[g]);
        }
        #pragma unroll
        for (int g = 0; g < NG; ++g)
            feval(zr[g], zi[g], Ar[g], Ai[g], NBr[g], NBi[g], NEG1, k5r[g], k5i[g]);

        // Stage-6 prep (last use of k2), then fold B-weighted k1,k3,k4,k5 into Z
        // BEFORE the k6 feval so k1..k5 die early (register pressure).
        #pragma unroll
        for (int g = 0; g < NG; ++g) {
            zr[g] = f2fma(HA61, k1r[g], Zr[g]); zr[g] = f2fma(HA62, k2r[g], zr[g]);
            zr[g] = f2fma(HA63, k3r[g], zr[g]); zr[g] = f2fma(HA64, k4r[g], zr[g]);
            zr[g] = f2fma(HA65, k5r[g], zr[g]);
            zi[g] = f2fma(HA61, k1i[g], Zi[g]); zi[g] = f2fma(HA62, k2i[g], zi[g]);
            zi[g] = f2fma(HA63, k3i[g], zi[g]); zi[g] = f2fma(HA64, k4i[g], zi[g]);
            zi[g] = f2fma(HA65, k5i[g], zi[g]);

            Zr[g] = f2fma(HB1, k1r[g], Zr[g]); Zr[g] = f2fma(HB3, k3r[g], Zr[g]);
            Zr[g] = f2fma(HB4, k4r[g], Zr[g]); Zr[g] = f2fma(HB5, k5r[g], Zr[g]);
            Zi[g] = f2fma(HB1, k1i[g], Zi[g]); Zi[g] = f2fma(HB3, k3i[g], Zi[g]);
            Zi[g] = f2fma(HB4, k4i[g], Zi[g]); Zi[g] = f2fma(HB5, k5i[g], Zi[g]);
        }
        #pragma unroll
        for (int g = 0; g < NG; ++g)
            feval(zr[g], zi[g], Ar[g], Ai[g], NBr[g], NBi[g], NEG1, k6r[g], k6i[g]);

        #pragma unroll
        for (int g = 0; g < NG; ++g) {
            Zr[g] = f2fma(HB6, k6r[g], Zr[g]);
            Zi[g] = f2fma(HB6, k6i[g], Zi[g]);
        }
    }

    // Output: stacked [real (N), imag (N)]
    #pragma unroll
    for (int g = 0; g < NG; ++g) {
        if (ok[g]) {
            out[idx[g]]          = up(Zr[g]);
            out[npairs + idx[g]] = up(Zi[g]);
        }
    }
}

extern "C" void kernel_launch(void* const* d_in, const int* in_sizes, int n_in,
                              void* d_out, int out_size) {
    const float2* re_z = (const float2*)d_in[0];
    const float2* im_z = (const float2*)d_in[1];
    const float2* re_a = (const float2*)d_in[2];
    const float2* im_a = (const float2*)d_in[3];
    const float2* re_b = (const float2*)d_in[4];
    const float2* im_b = (const float2*)d_in[5];
    const int*    unts = (const int*)d_in[7];
    float2* out = (float2*)d_out;

    int n = in_sizes[0];               // 2048*2048 elements
    int npairs = n / 2;                // f32x2 pairs
    int gstride = (npairs + NG - 1) / NG;
    int threads = 256;
    int blocks = (gstride + threads - 1) / threads;
    hopf_dopri5_kernel<<<blocks, threads>>>(re_z, im_z, re_a, im_a, re_b, im_b,
                                            unts, out, npairs, gstride);
}